// round 2
// baseline (speedup 1.0000x reference)
#include <cuda_runtime.h>
#include <cuda_bf16.h>

// Problem constants
#define BATCH 16
#define SEQ   4096
#define HDIM  1024
#define HN    16      // heads
#define HD    64      // head dim

// ---------------------------------------------------------------------------
// Scratch (device globals: no allocation allowed)
// ---------------------------------------------------------------------------
__device__ float g_q[BATCH * HDIM];          // q = query @ Wq^T + bq
__device__ float g_w[BATCH * HN * HDIM];     // w[b,h,:] = (1/32) Wk_h^T q_h
__device__ float g_c[BATCH * HN];            // (1/32) q_h . bk_h
__device__ float g_att[BATCH * SEQ * HN];    // softmax attention [b,s,h]
__device__ float g_u[BATCH * HN * HDIM];     // u[b,h,:] = sum_s att * value_row
__device__ float g_A[BATCH * HN];            // A[b,h]   = sum_s att
__device__ float g_o1[BATCH * HDIM];         // out before final projection

// ---------------------------------------------------------------------------
// f32x2 helpers (packed FFMA2)
// ---------------------------------------------------------------------------
__device__ __forceinline__ void fma2(unsigned long long &d,
                                     unsigned long long a,
                                     unsigned long long b) {
    asm("fma.rn.f32x2 %0, %1, %2, %0;" : "+l"(d) : "l"(a), "l"(b));
}
__device__ __forceinline__ float2 unpack2(unsigned long long v) {
    float2 f;
    asm("mov.b64 {%0, %1}, %2;" : "=f"(f.x), "=f"(f.y) : "l"(v));
    return f;
}
__device__ __forceinline__ unsigned long long pack_dup(float a) {
    unsigned long long r;
    asm("mov.b64 %0, {%1, %1};" : "=l"(r) : "f"(a));
    return r;
}

// ---------------------------------------------------------------------------
// K1: q[b,i] = query[b,:] . Wq[i,:] + bq[i]   (warp per output)
// ---------------------------------------------------------------------------
__global__ void k1_q(const float* __restrict__ query,
                     const float* __restrict__ Wq,
                     const float* __restrict__ bq) {
    int gw   = (blockIdx.x * blockDim.x + threadIdx.x) >> 5;
    int lane = threadIdx.x & 31;
    if (gw >= BATCH * HDIM) return;
    int b = gw >> 10, i = gw & 1023;
    const float4* qr = (const float4*)(query + b * HDIM);
    const float4* wr = (const float4*)(Wq + (size_t)i * HDIM);
    float acc = 0.f;
#pragma unroll
    for (int t = 0; t < 8; t++) {
        float4 a = qr[t * 32 + lane];
        float4 w = wr[t * 32 + lane];
        acc += a.x * w.x + a.y * w.y + a.z * w.z + a.w * w.w;
    }
#pragma unroll
    for (int o = 16; o > 0; o >>= 1) acc += __shfl_xor_sync(~0u, acc, o);
    if (lane == 0) g_q[gw] = acc + bq[i];
}

// ---------------------------------------------------------------------------
// K2: w[b,h,j] = (1/32) sum_d q[b,h*64+d] * Wk[h*64+d, j];  also zeros g_u/g_A
// ---------------------------------------------------------------------------
__global__ void k2_w(const float* __restrict__ Wk,
                     const float* __restrict__ bk) {
    int h = blockIdx.x >> 4;
    int b = blockIdx.x & 15;
    int tid = threadIdx.x;

    // zero accumulators (65536 threads total, g_u = 65536 float4)
    int gtid = blockIdx.x * 256 + tid;
    ((float4*)g_u)[gtid] = make_float4(0.f, 0.f, 0.f, 0.f);
    if (gtid < BATCH * HN) g_A[gtid] = 0.f;

    __shared__ float qh[HD];
    if (tid < HD) qh[tid] = g_q[b * HDIM + h * HD + tid];
    __syncthreads();

    float4 acc = make_float4(0.f, 0.f, 0.f, 0.f);
    const float4* wk = (const float4*)(Wk + (size_t)(h * HD) * HDIM) + tid;
#pragma unroll 8
    for (int d = 0; d < HD; d++) {
        float4 v = wk[d * 256];
        float  s = qh[d];
        acc.x += s * v.x; acc.y += s * v.y; acc.z += s * v.z; acc.w += s * v.w;
    }
    const float scale = 0.03125f;  // 1/sqrt(1024)
    acc.x *= scale; acc.y *= scale; acc.z *= scale; acc.w *= scale;
    ((float4*)(g_w + (b * HN + h) * HDIM))[tid] = acc;

    if (tid == 0) {
        float cc = 0.f;
        for (int d = 0; d < HD; d++) cc += qh[d] * bk[h * HD + d];
        g_c[b * HN + h] = cc * scale;
    }
}

// ---------------------------------------------------------------------------
// K3a: scores + softmax -> g_att.
//  grid (16 chunks, 16 b), 256 thr. w[b] staged in smem (64KB, 1 CTA/SM).
//  Each warp processes 4 rows per pass: w LDS amortized 4x. Lane-transpose
//  butterfly reduce puts head (lane&15) in each lane; softmax over lanes.
//  No barriers inside the main loop.
// ---------------------------------------------------------------------------
__global__ __launch_bounds__(256, 1)
void k3a_scores(const float* __restrict__ key) {
    extern __shared__ float smem_raw[];
    float* w_s = smem_raw;            // 16384 floats
    float* c_s = w_s + HN * HDIM;     // 16 floats

    const int b = blockIdx.y;
    const int chunk = blockIdx.x;
    const int tid = threadIdx.x;
    const int wq = tid >> 5;
    const int lane = tid & 31;

    {
        const float4* src = (const float4*)(g_w + b * HN * HDIM);
        float4* dst = (float4*)w_s;
        for (int i = tid; i < HN * HDIM / 4; i += 256) dst[i] = src[i];
        if (tid < HN) c_s[tid] = g_c[b * HN + tid];
    }
    __syncthreads();

    const float* keyb = key + (size_t)b * SEQ * HDIM;
    float* attb = g_att + (size_t)b * SEQ * HN;
    const int row0 = chunk << 8;

    for (int pass = 0; pass < 8; pass++) {
        const int rbase = row0 + pass * 32 + wq * 4;
        const ulonglong2* kp[4];
#pragma unroll
        for (int r = 0; r < 4; r++)
            kp[r] = (const ulonglong2*)(keyb + (size_t)(rbase + r) * HDIM) + lane;

        unsigned long long p2[4][16];
#pragma unroll
        for (int r = 0; r < 4; r++)
#pragma unroll
            for (int h = 0; h < 16; h++) p2[r][h] = 0ULL;

        // double-buffered key loads (MLP across rows + lookahead)
        ulonglong2 kv[4], kvn[4];
#pragma unroll
        for (int r = 0; r < 4; r++) kv[r] = kp[r][0];

#pragma unroll
        for (int kk = 0; kk < 8; kk++) {
            if (kk < 7) {
#pragma unroll
                for (int r = 0; r < 4; r++) kvn[r] = kp[r][(kk + 1) * 32];
            }
            const ulonglong2* wp = (const ulonglong2*)w_s + kk * 32 + lane;
#pragma unroll
            for (int h = 0; h < 16; h++) {
                ulonglong2 wv = wp[h * 256];  // + h*1024 floats
#pragma unroll
                for (int r = 0; r < 4; r++) {
                    fma2(p2[r][h], kv[r].x, wv.x);
                    fma2(p2[r][h], kv[r].y, wv.y);
                }
            }
            if (kk < 7) {
#pragma unroll
                for (int r = 0; r < 4; r++) kv[r] = kvn[r];
            }
        }

        // per-row: transpose-reduce, softmax over heads, store att
#pragma unroll
        for (int r = 0; r < 4; r++) {
            float v[16];
#pragma unroll
            for (int h = 0; h < 16; h++) {
                float2 f = unpack2(p2[r][h]);
                v[h] = f.x + f.y;
            }
            // symmetrize halves
#pragma unroll
            for (int h = 0; h < 16; h++) v[h] += __shfl_xor_sync(~0u, v[h], 16);
            // split steps: after these, lane l holds sum for head (l & 15)
            {
                const bool hi = (lane & 8) != 0;
#pragma unroll
                for (int i = 0; i < 8; i++) {
                    float keep = hi ? v[i + 8] : v[i];
                    float send = hi ? v[i] : v[i + 8];
                    v[i] = keep + __shfl_xor_sync(~0u, send, 8);
                }
            }
            {
                const bool hi = (lane & 4) != 0;
#pragma unroll
                for (int i = 0; i < 4; i++) {
                    float keep = hi ? v[i + 4] : v[i];
                    float send = hi ? v[i] : v[i + 4];
                    v[i] = keep + __shfl_xor_sync(~0u, send, 4);
                }
            }
            {
                const bool hi = (lane & 2) != 0;
#pragma unroll
                for (int i = 0; i < 2; i++) {
                    float keep = hi ? v[i + 2] : v[i];
                    float send = hi ? v[i] : v[i + 2];
                    v[i] = keep + __shfl_xor_sync(~0u, send, 2);
                }
            }
            {
                const bool hi = (lane & 1) != 0;
                float keep = hi ? v[1] : v[0];
                float send = hi ? v[0] : v[1];
                v[0] = keep + __shfl_xor_sync(~0u, send, 1);
            }
            float sc = v[0] + c_s[lane & 15];
            // softmax across the 16-lane group (duplicated in both halves)
            float m = sc;
#pragma unroll
            for (int s = 1; s < 16; s <<= 1) m = fmaxf(m, __shfl_xor_sync(~0u, m, s));
            float e = __expf(sc - m);
            float sum = e;
#pragma unroll
            for (int s = 1; s < 16; s <<= 1) sum += __shfl_xor_sync(~0u, sum, s);
            float att = __fdividef(e, sum);
            if (lane < 16) attb[(size_t)(rbase + r) * HN + lane] = att;
        }
    }
}

// ---------------------------------------------------------------------------
// K3b: u[b,h,j] += sum_s att[b,s,h] * value[b,s,j]
//  grid (16 chunks, 16 b), 256 thr, 2 CTA/SM. att staged+packed in smem,
//  value loads batched 8-deep, register u accumulators, atomic flush.
// ---------------------------------------------------------------------------
__global__ __launch_bounds__(256, 2)
void k3b_accum(const float* __restrict__ value) {
    __shared__ unsigned long long att_s[128];   // 8 rows x 16 heads, packed {a,a}

    const int b = blockIdx.y;
    const int chunk = blockIdx.x;
    const int tid = threadIdx.x;
    const int wq = tid >> 5;
    const int lane = tid & 31;
    const int j0 = (wq << 7) + (lane << 2);

    const float* valb = value + (size_t)b * SEQ * HDIM;
    const float* attb = g_att + (size_t)b * SEQ * HN;
    const int row0 = chunk << 8;

    unsigned long long u2[32];
#pragma unroll
    for (int i = 0; i < 32; i++) u2[i] = 0ULL;
    float a_loc = 0.f;

    for (int g = 0; g < 32; g++) {
        // stage att for 8 rows (coalesced 128-float read, pack {a,a})
        if (tid < 128) {
            float a = attb[(size_t)(row0 + g * 8 + (tid >> 4)) * HN + (tid & 15)];
            att_s[tid] = pack_dup(a);
        }
        __syncthreads();

        ulonglong2 vv[8];
#pragma unroll
        for (int r = 0; r < 8; r++)
            vv[r] = *(const ulonglong2*)(valb + (size_t)(row0 + g * 8 + r) * HDIM + j0);

#pragma unroll
        for (int r = 0; r < 8; r++) {
#pragma unroll
            for (int h = 0; h < 16; h++) {
                unsigned long long a2 = att_s[r * 16 + h];   // broadcast LDS.64
                fma2(u2[2 * h + 0], a2, vv[r].x);
                fma2(u2[2 * h + 1], a2, vv[r].y);
            }
        }
        if (tid < 16) {
#pragma unroll
            for (int r = 0; r < 8; r++) a_loc += ((const float*)att_s)[(r * 16 + tid) * 2];
        }
        __syncthreads();
    }

    float* ubase = g_u + (b * HN) * HDIM + j0;
#pragma unroll
    for (int h = 0; h < 16; h++) {
        float2 lo = unpack2(u2[2 * h + 0]);
        float2 hi = unpack2(u2[2 * h + 1]);
        atomicAdd(ubase + (h << 10) + 0, lo.x);
        atomicAdd(ubase + (h << 10) + 1, lo.y);
        atomicAdd(ubase + (h << 10) + 2, hi.x);
        atomicAdd(ubase + (h << 10) + 3, hi.y);
    }
    if (tid < 16) atomicAdd(&g_A[b * HN + tid], a_loc);
}

// ---------------------------------------------------------------------------
// K4: o1[b,j] = Wv[j,:] . u[b, j/64, :] + bv[j] * A[b, j/64]   warp per (j,b)
// ---------------------------------------------------------------------------
__global__ void k4_out(const float* __restrict__ Wv,
                       const float* __restrict__ bv) {
    int gw   = (blockIdx.x * blockDim.x + threadIdx.x) >> 5;
    int lane = threadIdx.x & 31;
    if (gw >= HDIM * BATCH) return;
    int b = gw & 15, j = gw >> 4, h = j >> 6;
    const float4* wr = (const float4*)(Wv + (size_t)j * HDIM);
    const float4* ur = (const float4*)(g_u + (b * HN + h) * HDIM);
    float acc = 0.f;
#pragma unroll
    for (int t = 0; t < 8; t++) {
        float4 w = wr[t * 32 + lane];
        float4 u = ur[t * 32 + lane];
        acc += w.x * u.x + w.y * u.y + w.z * u.z + w.w * u.w;
    }
#pragma unroll
    for (int o = 16; o > 0; o >>= 1) acc += __shfl_xor_sync(~0u, acc, o);
    if (lane == 0) g_o1[b * HDIM + j] = acc + bv[j] * g_A[b * HN + h];
}

// ---------------------------------------------------------------------------
// K5: res[b,i] = Wf[i,:] . o1[b,:] + bf[i]   warp per (i,b)
// ---------------------------------------------------------------------------
__global__ void k5_final(const float* __restrict__ Wf,
                         const float* __restrict__ bf,
                         float* __restrict__ res) {
    int gw   = (blockIdx.x * blockDim.x + threadIdx.x) >> 5;
    int lane = threadIdx.x & 31;
    if (gw >= HDIM * BATCH) return;
    int b = gw & 15, i = gw >> 4;
    const float4* wr = (const float4*)(Wf + (size_t)i * HDIM);
    const float4* orow = (const float4*)(g_o1 + b * HDIM);
    float acc = 0.f;
#pragma unroll
    for (int t = 0; t < 8; t++) {
        float4 w = wr[t * 32 + lane];
        float4 o = orow[t * 32 + lane];
        acc += w.x * o.x + w.y * o.y + w.z * o.z + w.w * o.w;
    }
#pragma unroll
    for (int o = 16; o > 0; o >>= 1) acc += __shfl_xor_sync(~0u, acc, o);
    if (lane == 0) res[b * HDIM + i] = acc + bf[i];
}

// ---------------------------------------------------------------------------
// launch
// ---------------------------------------------------------------------------
extern "C" void kernel_launch(void* const* d_in, const int* in_sizes, int n_in,
                              void* d_out, int out_size) {
    const float* query = (const float*)d_in[0];
    const float* key_  = (const float*)d_in[1];
    const float* value = (const float*)d_in[2];
    const float* Wq    = (const float*)d_in[3];
    const float* bq    = (const float*)d_in[4];
    const float* Wk    = (const float*)d_in[5];
    const float* bk    = (const float*)d_in[6];
    const float* Wv    = (const float*)d_in[7];
    const float* bv    = (const float*)d_in[8];
    const float* Wf    = (const float*)d_in[9];
    const float* bf    = (const float*)d_in[10];
    float* out = (float*)d_out;

    const int k3a_smem = (HN * HDIM + 16) * 4;   // 65600 B
    static bool attr_set = false;
    if (!attr_set) {
        cudaFuncSetAttribute(k3a_scores, cudaFuncAttributeMaxDynamicSharedMemorySize, k3a_smem);
        attr_set = true;
    }

    k1_q<<<(BATCH * HDIM * 32 + 255) / 256, 256>>>(query, Wq, bq);
    k2_w<<<HN * BATCH, 256>>>(Wk, bk);
    {
        dim3 grid(SEQ / 256, BATCH);
        k3a_scores<<<grid, 256, k3a_smem>>>(key_);
        k3b_accum<<<grid, 256>>>(value);
    }
    k4_out<<<(HDIM * BATCH * 32 + 255) / 256, 256>>>(Wv, bv);
    k5_final<<<(HDIM * BATCH * 32 + 255) / 256, 256>>>(Wf, bf, out);
}

// round 3
// speedup vs baseline: 2.3283x; 2.3283x over previous
#include <cuda_runtime.h>
#include <cuda_bf16.h>

// Problem constants
#define BATCH 16
#define SEQ   4096
#define HDIM  1024
#define HN    16      // heads
#define HD    64      // head dim

// ---------------------------------------------------------------------------
// Scratch (device globals: no allocation allowed)
// ---------------------------------------------------------------------------
__device__ float g_q[BATCH * HDIM];          // q = query @ Wq^T + bq
__device__ float g_w[BATCH * HN * HDIM];     // w[b,h,:] = (1/32) Wk_h^T q_h
__device__ float g_c[BATCH * HN];            // (1/32) q_h . bk_h
__device__ float g_att[BATCH * SEQ * HN];    // softmax attention [b,s,h]
__device__ float g_u[BATCH * HN * HDIM];     // u[b,h,:] = sum_s att * value_row
__device__ float g_A[BATCH * HN];            // A[b,h]   = sum_s att
__device__ float g_o1[BATCH * HDIM];         // out before final projection

// ---------------------------------------------------------------------------
// f32x2 helpers (packed FFMA2)
// ---------------------------------------------------------------------------
__device__ __forceinline__ void fma2(unsigned long long &d,
                                     unsigned long long a,
                                     unsigned long long b) {
    asm("fma.rn.f32x2 %0, %1, %2, %0;" : "+l"(d) : "l"(a), "l"(b));
}
__device__ __forceinline__ float2 unpack2(unsigned long long v) {
    float2 f;
    asm("mov.b64 {%0, %1}, %2;" : "=f"(f.x), "=f"(f.y) : "l"(v));
    return f;
}
__device__ __forceinline__ unsigned long long pack_dup(float a) {
    unsigned long long r;
    asm("mov.b64 %0, {%1, %1};" : "=l"(r) : "f"(a));
    return r;
}

// ---------------------------------------------------------------------------
// K1: q[b,i] = query[b,:] . Wq[i,:] + bq[i]   (warp per output)
// ---------------------------------------------------------------------------
__global__ void k1_q(const float* __restrict__ query,
                     const float* __restrict__ Wq,
                     const float* __restrict__ bq) {
    int gw   = (blockIdx.x * blockDim.x + threadIdx.x) >> 5;
    int lane = threadIdx.x & 31;
    if (gw >= BATCH * HDIM) return;
    int b = gw >> 10, i = gw & 1023;
    const float4* qr = (const float4*)(query + b * HDIM);
    const float4* wr = (const float4*)(Wq + (size_t)i * HDIM);
    float acc = 0.f;
#pragma unroll
    for (int t = 0; t < 8; t++) {
        float4 a = qr[t * 32 + lane];
        float4 w = wr[t * 32 + lane];
        acc += a.x * w.x + a.y * w.y + a.z * w.z + a.w * w.w;
    }
#pragma unroll
    for (int o = 16; o > 0; o >>= 1) acc += __shfl_xor_sync(~0u, acc, o);
    if (lane == 0) g_q[gw] = acc + bq[i];
}

// ---------------------------------------------------------------------------
// K2: w[b,h,j] = (1/32) sum_d q[b,h*64+d] * Wk[h*64+d, j];  also zeros g_u/g_A
// ---------------------------------------------------------------------------
__global__ void k2_w(const float* __restrict__ Wk,
                     const float* __restrict__ bk) {
    int h = blockIdx.x >> 4;
    int b = blockIdx.x & 15;
    int tid = threadIdx.x;

    int gtid = blockIdx.x * 256 + tid;
    ((float4*)g_u)[gtid] = make_float4(0.f, 0.f, 0.f, 0.f);
    if (gtid < BATCH * HN) g_A[gtid] = 0.f;

    __shared__ float qh[HD];
    if (tid < HD) qh[tid] = g_q[b * HDIM + h * HD + tid];
    __syncthreads();

    float4 acc = make_float4(0.f, 0.f, 0.f, 0.f);
    const float4* wk = (const float4*)(Wk + (size_t)(h * HD) * HDIM) + tid;
#pragma unroll 8
    for (int d = 0; d < HD; d++) {
        float4 v = wk[d * 256];
        float  s = qh[d];
        acc.x += s * v.x; acc.y += s * v.y; acc.z += s * v.z; acc.w += s * v.w;
    }
    const float scale = 0.03125f;  // 1/sqrt(1024)
    acc.x *= scale; acc.y *= scale; acc.z *= scale; acc.w *= scale;
    ((float4*)(g_w + (b * HN + h) * HDIM))[tid] = acc;

    if (tid == 0) {
        float cc = 0.f;
        for (int d = 0; d < HD; d++) cc += qh[d] * bk[h * HD + d];
        g_c[b * HN + h] = cc * scale;
    }
}

// ---------------------------------------------------------------------------
// K3a: scores + softmax -> g_att.
//  grid (16 chunks, 16 b), 256 thr, 2 CTA/SM (regs capped at 128).
//  Warp PAIR (2q, 2q+1) shares 4 rows; each warp computes 8 of the 16 heads
//  => accumulators p2[4][8] = 64 regs, no spill, w LDS amortized 4x over rows
//  and 2x over head-split. Halves combined in smem; softmax stage maps
//  threads 1:1 to (row, head) for a fully coalesced att store.
// ---------------------------------------------------------------------------
__global__ __launch_bounds__(256, 2)
void k3a_scores(const float* __restrict__ key) {
    extern __shared__ float smem_raw[];
    float* w_s     = smem_raw;            // 16384 floats
    float* c_s     = w_s + HN * HDIM;     // 16 floats
    float* score_s = c_s + 16;            // 256 floats (16 rows x 16 heads)

    const int b     = blockIdx.y;
    const int chunk = blockIdx.x;
    const int tid   = threadIdx.x;
    const int wq    = tid >> 5;
    const int lane  = tid & 31;
    const int rgrp  = wq >> 1;   // 0..3 : which 4-row group
    const int half  = wq & 1;    // 0..1 : which 8 heads

    {
        const float4* src = (const float4*)(g_w + b * HN * HDIM);
        float4* dst = (float4*)w_s;
        for (int i = tid; i < HN * HDIM / 4; i += 256) dst[i] = src[i];
        if (tid < HN) c_s[tid] = g_c[b * HN + tid];
    }
    __syncthreads();

    const float* keyb = key + (size_t)b * SEQ * HDIM;
    float* attb = g_att + (size_t)b * SEQ * HN;
    const int row0 = chunk << 8;

    for (int pass = 0; pass < 16; pass++) {
        const int rbase = row0 + pass * 16 + rgrp * 4;

        unsigned long long p2[4][8];
#pragma unroll
        for (int r = 0; r < 4; r++)
#pragma unroll
            for (int h = 0; h < 8; h++) p2[r][h] = 0ULL;

        const ulonglong2* wbase = (const ulonglong2*)w_s + (half * 8) * 256 + lane;

#pragma unroll
        for (int kk = 0; kk < 8; kk++) {
            ulonglong2 kv[4];
#pragma unroll
            for (int r = 0; r < 4; r++)
                kv[r] = *((const ulonglong2*)(keyb + (size_t)(rbase + r) * HDIM)
                          + kk * 32 + lane);
            const ulonglong2* wp = wbase + kk * 32;
#pragma unroll
            for (int h = 0; h < 8; h++) {
                ulonglong2 wv = wp[h * 256];
#pragma unroll
                for (int r = 0; r < 4; r++) {
                    fma2(p2[r][h], kv[r].x, wv.x);
                    fma2(p2[r][h], kv[r].y, wv.y);
                }
            }
        }

        // per-row: reduce 8 head-partials across 32 lanes -> lane (l&7) = head
#pragma unroll
        for (int r = 0; r < 4; r++) {
            float v[8];
#pragma unroll
            for (int h = 0; h < 8; h++) {
                float2 f = unpack2(p2[r][h]);
                v[h] = f.x + f.y;
            }
#pragma unroll
            for (int h = 0; h < 8; h++) v[h] += __shfl_xor_sync(~0u, v[h], 16);
#pragma unroll
            for (int h = 0; h < 8; h++) v[h] += __shfl_xor_sync(~0u, v[h], 8);
            {
                const bool hi = (lane & 4) != 0;
#pragma unroll
                for (int i = 0; i < 4; i++) {
                    float keep = hi ? v[i + 4] : v[i];
                    float send = hi ? v[i] : v[i + 4];
                    v[i] = keep + __shfl_xor_sync(~0u, send, 4);
                }
            }
            {
                const bool hi = (lane & 2) != 0;
#pragma unroll
                for (int i = 0; i < 2; i++) {
                    float keep = hi ? v[i + 2] : v[i];
                    float send = hi ? v[i] : v[i + 2];
                    v[i] = keep + __shfl_xor_sync(~0u, send, 2);
                }
            }
            {
                const bool hi = (lane & 1) != 0;
                float keep = hi ? v[1] : v[0];
                float send = hi ? v[0] : v[1];
                v[0] = keep + __shfl_xor_sync(~0u, send, 1);
            }
            if (lane < 8)
                score_s[(rgrp * 4 + r) * 16 + half * 8 + lane] = v[0];
        }
        __syncthreads();

        // softmax: thread t = (row t>>4, head t&15); 16-lane shfl groups
        {
            float sc = score_s[tid] + c_s[tid & 15];
            float m = sc;
#pragma unroll
            for (int s = 8; s > 0; s >>= 1) m = fmaxf(m, __shfl_xor_sync(~0u, m, s));
            float e = __expf(sc - m);
            float sum = e;
#pragma unroll
            for (int s = 8; s > 0; s >>= 1) sum += __shfl_xor_sync(~0u, sum, s);
            attb[(size_t)(row0 + pass * 16) * HN + tid] = __fdividef(e, sum);
        }
        __syncthreads();
    }
}

// ---------------------------------------------------------------------------
// K3b: u[b,h,j] += sum_s att[b,s,h] * value[b,s,j]
//  grid (16 chunks, 16 b), 256 thr, 2 CTA/SM. att staged 32 rows per barrier
//  pair (16 barriers total), value loads batched 8-deep, register u
//  accumulators, atomic flush.
// ---------------------------------------------------------------------------
__global__ __launch_bounds__(256, 2)
void k3b_accum(const float* __restrict__ value) {
    __shared__ unsigned long long att_s[512];   // 32 rows x 16 heads, packed {a,a}

    const int b = blockIdx.y;
    const int chunk = blockIdx.x;
    const int tid = threadIdx.x;
    const int wq = tid >> 5;
    const int lane = tid & 31;
    const int j0 = (wq << 7) + (lane << 2);

    const float* valb = value + (size_t)b * SEQ * HDIM;
    const float* attb = g_att + (size_t)b * SEQ * HN;
    const int row0 = chunk << 8;

    unsigned long long u2[32];
#pragma unroll
    for (int i = 0; i < 32; i++) u2[i] = 0ULL;
    float a_loc = 0.f;

    for (int G = 0; G < 8; G++) {
        const int r32 = row0 + G * 32;
        // stage att for 32 rows: 512 consecutive floats, coalesced
        {
            const float* asrc = attb + (size_t)r32 * HN;
            att_s[tid]       = pack_dup(asrc[tid]);
            att_s[tid + 256] = pack_dup(asrc[tid + 256]);
        }
        __syncthreads();

#pragma unroll
        for (int g4 = 0; g4 < 4; g4++) {
            const int rb = r32 + g4 * 8;
            ulonglong2 vv[8];
#pragma unroll
            for (int r = 0; r < 8; r++)
                vv[r] = *(const ulonglong2*)(valb + (size_t)(rb + r) * HDIM + j0);
#pragma unroll
            for (int r = 0; r < 8; r++) {
#pragma unroll
                for (int h = 0; h < 16; h++) {
                    unsigned long long a2 = att_s[(g4 * 8 + r) * 16 + h];
                    fma2(u2[2 * h + 0], a2, vv[r].x);
                    fma2(u2[2 * h + 1], a2, vv[r].y);
                }
            }
        }
        if (tid < 16) {
#pragma unroll
            for (int r = 0; r < 32; r++)
                a_loc += ((const float*)att_s)[(r * 16 + tid) * 2];
        }
        __syncthreads();
    }

    float* ubase = g_u + (b * HN) * HDIM + j0;
#pragma unroll
    for (int h = 0; h < 16; h++) {
        float2 lo = unpack2(u2[2 * h + 0]);
        float2 hi = unpack2(u2[2 * h + 1]);
        atomicAdd(ubase + (h << 10) + 0, lo.x);
        atomicAdd(ubase + (h << 10) + 1, lo.y);
        atomicAdd(ubase + (h << 10) + 2, hi.x);
        atomicAdd(ubase + (h << 10) + 3, hi.y);
    }
    if (tid < 16) atomicAdd(&g_A[b * HN + tid], a_loc);
}

// ---------------------------------------------------------------------------
// K4: o1[b,j] = Wv[j,:] . u[b, j/64, :] + bv[j] * A[b, j/64]   warp per (j,b)
// ---------------------------------------------------------------------------
__global__ void k4_out(const float* __restrict__ Wv,
                       const float* __restrict__ bv) {
    int gw   = (blockIdx.x * blockDim.x + threadIdx.x) >> 5;
    int lane = threadIdx.x & 31;
    if (gw >= HDIM * BATCH) return;
    int b = gw & 15, j = gw >> 4, h = j >> 6;
    const float4* wr = (const float4*)(Wv + (size_t)j * HDIM);
    const float4* ur = (const float4*)(g_u + (b * HN + h) * HDIM);
    float acc = 0.f;
#pragma unroll
    for (int t = 0; t < 8; t++) {
        float4 w = wr[t * 32 + lane];
        float4 u = ur[t * 32 + lane];
        acc += w.x * u.x + w.y * u.y + w.z * u.z + w.w * u.w;
    }
#pragma unroll
    for (int o = 16; o > 0; o >>= 1) acc += __shfl_xor_sync(~0u, acc, o);
    if (lane == 0) g_o1[b * HDIM + j] = acc + bv[j] * g_A[b * HN + h];
}

// ---------------------------------------------------------------------------
// K5: res[b,i] = Wf[i,:] . o1[b,:] + bf[i]   warp per (i,b)
// ---------------------------------------------------------------------------
__global__ void k5_final(const float* __restrict__ Wf,
                         const float* __restrict__ bf,
                         float* __restrict__ res) {
    int gw   = (blockIdx.x * blockDim.x + threadIdx.x) >> 5;
    int lane = threadIdx.x & 31;
    if (gw >= HDIM * BATCH) return;
    int b = gw & 15, i = gw >> 4;
    const float4* wr = (const float4*)(Wf + (size_t)i * HDIM);
    const float4* orow = (const float4*)(g_o1 + b * HDIM);
    float acc = 0.f;
#pragma unroll
    for (int t = 0; t < 8; t++) {
        float4 w = wr[t * 32 + lane];
        float4 o = orow[t * 32 + lane];
        acc += w.x * o.x + w.y * o.y + w.z * o.z + w.w * o.w;
    }
#pragma unroll
    for (int o = 16; o > 0; o >>= 1) acc += __shfl_xor_sync(~0u, acc, o);
    if (lane == 0) res[b * HDIM + i] = acc + bf[i];
}

// ---------------------------------------------------------------------------
// launch
// ---------------------------------------------------------------------------
extern "C" void kernel_launch(void* const* d_in, const int* in_sizes, int n_in,
                              void* d_out, int out_size) {
    const float* query = (const float*)d_in[0];
    const float* key_  = (const float*)d_in[1];
    const float* value = (const float*)d_in[2];
    const float* Wq    = (const float*)d_in[3];
    const float* bq    = (const float*)d_in[4];
    const float* Wk    = (const float*)d_in[5];
    const float* bk    = (const float*)d_in[6];
    const float* Wv    = (const float*)d_in[7];
    const float* bv    = (const float*)d_in[8];
    const float* Wf    = (const float*)d_in[9];
    const float* bf    = (const float*)d_in[10];
    float* out = (float*)d_out;

    const int k3a_smem = (HN * HDIM + 16 + 256) * 4;   // 66624 B
    static bool attr_set = false;
    if (!attr_set) {
        cudaFuncSetAttribute(k3a_scores, cudaFuncAttributeMaxDynamicSharedMemorySize, k3a_smem);
        attr_set = true;
    }

    k1_q<<<(BATCH * HDIM * 32 + 255) / 256, 256>>>(query, Wq, bq);
    k2_w<<<HN * BATCH, 256>>>(Wk, bk);
    {
        dim3 grid(SEQ / 256, BATCH);
        k3a_scores<<<grid, 256, k3a_smem>>>(key_);
        k3b_accum<<<grid, 256>>>(value);
    }
    k4_out<<<(HDIM * BATCH * 32 + 255) / 256, 256>>>(Wv, bv);
    k5_final<<<(HDIM * BATCH * 32 + 255) / 256, 256>>>(Wf, bf, out);
}

// round 4
// speedup vs baseline: 2.4469x; 1.0509x over previous
#include <cuda_runtime.h>
#include <cuda_bf16.h>

// Problem constants
#define BATCH 16
#define SEQ   4096
#define HDIM  1024
#define HN    16      // heads
#define HD    64      // head dim

// ---------------------------------------------------------------------------
// Scratch (device globals: no allocation allowed)
// ---------------------------------------------------------------------------
__device__ float g_q[BATCH * HDIM];          // q = query @ Wq^T + bq
__device__ float g_w[BATCH * HN * HDIM];     // w[b,h,:] = (1/32) Wk_h^T q_h
__device__ float g_c[BATCH * HN];            // (1/32) q_h . bk_h
__device__ float g_att[BATCH * SEQ * HN];    // softmax attention [b,s,h]
__device__ float g_u[BATCH * HN * HDIM];     // u[b,h,:] = sum_s att * value_row
__device__ float g_A[BATCH * HN];            // A[b,h]   = sum_s att
__device__ float g_o1[BATCH * HDIM];         // out before final projection

// ---------------------------------------------------------------------------
// f32x2 helpers (packed FFMA2)
// ---------------------------------------------------------------------------
__device__ __forceinline__ void fma2(unsigned long long &d,
                                     unsigned long long a,
                                     unsigned long long b) {
    asm("fma.rn.f32x2 %0, %1, %2, %0;" : "+l"(d) : "l"(a), "l"(b));
}
__device__ __forceinline__ float2 unpack2(unsigned long long v) {
    float2 f;
    asm("mov.b64 {%0, %1}, %2;" : "=f"(f.x), "=f"(f.y) : "l"(v));
    return f;
}
__device__ __forceinline__ unsigned long long pack2(float a, float b) {
    unsigned long long r;
    asm("mov.b64 %0, {%1, %2};" : "=l"(r) : "f"(a), "f"(b));
    return r;
}
__device__ __forceinline__ unsigned long long pack_dup(float a) {
    unsigned long long r;
    asm("mov.b64 %0, {%1, %1};" : "=l"(r) : "f"(a));
    return r;
}
__device__ __forceinline__ unsigned smem_u32(const void* p) {
    unsigned a;
    asm("{ .reg .u64 t; cvta.to.shared.u64 t, %1; cvt.u32.u64 %0, t; }"
        : "=r"(a) : "l"(p));
    return a;
}
__device__ __forceinline__ void cp_async16(unsigned dst, const void* src) {
    asm volatile("cp.async.cg.shared.global [%0], [%1], 16;"
                 :: "r"(dst), "l"(src) : "memory");
}
__device__ __forceinline__ void cp_commit() {
    asm volatile("cp.async.commit_group;" ::: "memory");
}
__device__ __forceinline__ void cp_wait1() {
    asm volatile("cp.async.wait_group 1;" ::: "memory");
}

// ---------------------------------------------------------------------------
// K1: q[b,i] = query[b,:] . Wq[i,:] + bq[i]   (warp per output)
// ---------------------------------------------------------------------------
__global__ void k1_q(const float* __restrict__ query,
                     const float* __restrict__ Wq,
                     const float* __restrict__ bq) {
    int gw   = (blockIdx.x * blockDim.x + threadIdx.x) >> 5;
    int lane = threadIdx.x & 31;
    if (gw >= BATCH * HDIM) return;
    int b = gw >> 10, i = gw & 1023;
    const float4* qr = (const float4*)(query + b * HDIM);
    const float4* wr = (const float4*)(Wq + (size_t)i * HDIM);
    float acc = 0.f;
#pragma unroll
    for (int t = 0; t < 8; t++) {
        float4 a = qr[t * 32 + lane];
        float4 w = wr[t * 32 + lane];
        acc += a.x * w.x + a.y * w.y + a.z * w.z + a.w * w.w;
    }
#pragma unroll
    for (int o = 16; o > 0; o >>= 1) acc += __shfl_xor_sync(~0u, acc, o);
    if (lane == 0) g_q[gw] = acc + bq[i];
}

// ---------------------------------------------------------------------------
// K2: w[b,h,j] = (1/32) sum_d q[b,h*64+d] * Wk[h*64+d, j];  also zeros g_u/g_A
// ---------------------------------------------------------------------------
__global__ void k2_w(const float* __restrict__ Wk,
                     const float* __restrict__ bk) {
    int h = blockIdx.x >> 4;
    int b = blockIdx.x & 15;
    int tid = threadIdx.x;

    int gtid = blockIdx.x * 256 + tid;
    ((float4*)g_u)[gtid] = make_float4(0.f, 0.f, 0.f, 0.f);
    if (gtid < BATCH * HN) g_A[gtid] = 0.f;

    __shared__ float qh[HD];
    if (tid < HD) qh[tid] = g_q[b * HDIM + h * HD + tid];
    __syncthreads();

    float4 acc = make_float4(0.f, 0.f, 0.f, 0.f);
    const float4* wk = (const float4*)(Wk + (size_t)(h * HD) * HDIM) + tid;
#pragma unroll 8
    for (int d = 0; d < HD; d++) {
        float4 v = wk[d * 256];
        float  s = qh[d];
        acc.x += s * v.x; acc.y += s * v.y; acc.z += s * v.z; acc.w += s * v.w;
    }
    const float scale = 0.03125f;  // 1/sqrt(1024)
    acc.x *= scale; acc.y *= scale; acc.z *= scale; acc.w *= scale;
    ((float4*)(g_w + (b * HN + h) * HDIM))[tid] = acc;

    if (tid == 0) {
        float cc = 0.f;
        for (int d = 0; d < HD; d++) cc += qh[d] * bk[h * HD + d];
        g_c[b * HN + h] = cc * scale;
    }
}

// ---------------------------------------------------------------------------
// K3a v2: scores + softmax -> g_att, w REGISTER-RESIDENT, key streamed via
// cp.async double buffer.
//  grid (32 chunks of 128 rows, 16 b), 256 thr, 2 CTA/SM.
//  Warp sw owns j-slice [sw*128, +128). Lane = (head = l&15, jhalf = l>>4)
//  holds w[b][head][slice + jhalf*64 .. +64) in 32 packed f32x2 regs.
//  Key rows broadcast from smem (conflict-free). Reduction = 1 shfl + STS;
//  cross-warp combine fused into per-stage softmax (128 threads).
// ---------------------------------------------------------------------------
#define K3A_ROWS_PER_STAGE 8
#define K3A_STAGES 16            // 128 rows / 8
__global__ __launch_bounds__(256, 2)
void k3a_scores(const float* __restrict__ key) {
    extern __shared__ float smem_raw[];
    float* kbuf = smem_raw;                        // 2 x 8 rows x 1024 = 16384 floats
    float* part = kbuf + 2 * 8 * HDIM;             // 2 x 8 warps x 8 rows x 16 heads = 2048 floats
    float* c_s  = part + 2048;                     // 16 floats

    const int b     = blockIdx.y;
    const int chunk = blockIdx.x;
    const int tid   = threadIdx.x;
    const int sw    = tid >> 5;
    const int lane  = tid & 31;
    const int h     = lane & 15;
    const int jhalf = lane >> 4;
    const int slice_off = sw * 128 + jhalf * 64;   // lane's 64-float j window

    if (tid < HN) c_s[tid] = g_c[b * HN + tid];

    // load w fragment: 64 floats as 32 packed f32x2
    unsigned long long wreg[32];
    {
        const float4* wsrc = (const float4*)(g_w + (size_t)(b * HN + h) * HDIM + slice_off);
#pragma unroll
        for (int t = 0; t < 16; t++) {
            float4 f = wsrc[t];
            wreg[2 * t + 0] = pack2(f.x, f.y);
            wreg[2 * t + 1] = pack2(f.z, f.w);
        }
    }

    const float* keyb = key + (size_t)b * SEQ * HDIM;
    float* attb = g_att + (size_t)b * SEQ * HN;
    const int row0 = chunk * 128;

    const unsigned kbuf_addr = smem_u32(kbuf);

    // prologue: prefetch stages 0 and 1
#pragma unroll
    for (int s = 0; s < 2; s++) {
        const float* src = keyb + (size_t)(row0 + s * 8) * HDIM;
#pragma unroll
        for (int c = 0; c < 8; c++)
            cp_async16(kbuf_addr + (s * 8192 + c * 1024 + tid * 4) * 4,
                       src + c * 1024 + tid * 4);
        cp_commit();
    }

    for (int s = 0; s < K3A_STAGES; s++) {
        const int buf = s & 1;
        cp_wait1();                 // stage s resident (s+1 may be in flight)
        __syncthreads();

        // ---- scores for 8 rows from smem broadcast ----
        const float4* kb = (const float4*)(kbuf + buf * 8192) + (slice_off >> 2);
        float* pdst = part + buf * 1024 + sw * 128 + h;
#pragma unroll
        for (int r = 0; r < 8; r++) {
            unsigned long long acc = 0ULL;
            const float4* krow = kb + r * 256;
#pragma unroll
            for (int t = 0; t < 16; t++) {
                float4 kv = krow[t];
                fma2(acc, pack2(kv.x, kv.y), wreg[2 * t + 0]);
                fma2(acc, pack2(kv.z, kv.w), wreg[2 * t + 1]);
            }
            float2 fa = unpack2(acc);
            float f = fa.x + fa.y;
            f += __shfl_xor_sync(~0u, f, 16);   // combine j-halves
            if (lane < 16) pdst[r * 16] = f;    // part[buf][sw][r][h]
        }
        __syncthreads();   // partials visible; kbuf[buf] reads done

        // refill kbuf[buf] with stage s+2 (empty commit keeps group count sane)
        if (s + 2 < K3A_STAGES) {
            const float* src = keyb + (size_t)(row0 + (s + 2) * 8) * HDIM;
#pragma unroll
            for (int c = 0; c < 8; c++)
                cp_async16(kbuf_addr + (buf * 8192 + c * 1024 + tid * 4) * 4,
                           src + c * 1024 + tid * 4);
        }
        cp_commit();

        // ---- softmax: thread t<128 = (row t>>4, head t&15) ----
        if (tid < 128) {
            const int r = tid >> 4, hh = tid & 15;
            const float* psrc = part + buf * 1024 + r * 16 + hh;
            float sc = c_s[hh];
#pragma unroll
            for (int w8 = 0; w8 < 8; w8++) sc += psrc[w8 * 128];
            float m = sc;
#pragma unroll
            for (int o = 8; o > 0; o >>= 1) m = fmaxf(m, __shfl_xor_sync(~0u, m, o));
            float e = __expf(sc - m);
            float sum = e;
#pragma unroll
            for (int o = 8; o > 0; o >>= 1) sum += __shfl_xor_sync(~0u, sum, o);
            attb[(size_t)(row0 + s * 8) * HN + tid] = __fdividef(e, sum);
        }
    }
}

// ---------------------------------------------------------------------------
// K3b: u[b,h,j] += sum_s att[b,s,h] * value[b,s,j]   (unchanged from R3)
// ---------------------------------------------------------------------------
__global__ __launch_bounds__(256, 2)
void k3b_accum(const float* __restrict__ value) {
    __shared__ unsigned long long att_s[512];   // 32 rows x 16 heads, packed {a,a}

    const int b = blockIdx.y;
    const int chunk = blockIdx.x;
    const int tid = threadIdx.x;
    const int wq = tid >> 5;
    const int lane = tid & 31;
    const int j0 = (wq << 7) + (lane << 2);

    const float* valb = value + (size_t)b * SEQ * HDIM;
    const float* attb = g_att + (size_t)b * SEQ * HN;
    const int row0 = chunk << 8;

    unsigned long long u2[32];
#pragma unroll
    for (int i = 0; i < 32; i++) u2[i] = 0ULL;
    float a_loc = 0.f;

    for (int G = 0; G < 8; G++) {
        const int r32 = row0 + G * 32;
        {
            const float* asrc = attb + (size_t)r32 * HN;
            att_s[tid]       = pack_dup(asrc[tid]);
            att_s[tid + 256] = pack_dup(asrc[tid + 256]);
        }
        __syncthreads();

#pragma unroll
        for (int g4 = 0; g4 < 4; g4++) {
            const int rb = r32 + g4 * 8;
            ulonglong2 vv[8];
#pragma unroll
            for (int r = 0; r < 8; r++)
                vv[r] = *(const ulonglong2*)(valb + (size_t)(rb + r) * HDIM + j0);
#pragma unroll
            for (int r = 0; r < 8; r++) {
#pragma unroll
                for (int h = 0; h < 16; h++) {
                    unsigned long long a2 = att_s[(g4 * 8 + r) * 16 + h];
                    fma2(u2[2 * h + 0], a2, vv[r].x);
                    fma2(u2[2 * h + 1], a2, vv[r].y);
                }
            }
        }
        if (tid < 16) {
#pragma unroll
            for (int r = 0; r < 32; r++)
                a_loc += ((const float*)att_s)[(r * 16 + tid) * 2];
        }
        __syncthreads();
    }

    float* ubase = g_u + (b * HN) * HDIM + j0;
#pragma unroll
    for (int h = 0; h < 16; h++) {
        float2 lo = unpack2(u2[2 * h + 0]);
        float2 hi = unpack2(u2[2 * h + 1]);
        atomicAdd(ubase + (h << 10) + 0, lo.x);
        atomicAdd(ubase + (h << 10) + 1, lo.y);
        atomicAdd(ubase + (h << 10) + 2, hi.x);
        atomicAdd(ubase + (h << 10) + 3, hi.y);
    }
    if (tid < 16) atomicAdd(&g_A[b * HN + tid], a_loc);
}

// ---------------------------------------------------------------------------
// K4: o1[b,j] = Wv[j,:] . u[b, j/64, :] + bv[j] * A[b, j/64]   warp per (j,b)
// ---------------------------------------------------------------------------
__global__ void k4_out(const float* __restrict__ Wv,
                       const float* __restrict__ bv) {
    int gw   = (blockIdx.x * blockDim.x + threadIdx.x) >> 5;
    int lane = threadIdx.x & 31;
    if (gw >= HDIM * BATCH) return;
    int b = gw & 15, j = gw >> 4, h = j >> 6;
    const float4* wr = (const float4*)(Wv + (size_t)j * HDIM);
    const float4* ur = (const float4*)(g_u + (b * HN + h) * HDIM);
    float acc = 0.f;
#pragma unroll
    for (int t = 0; t < 8; t++) {
        float4 w = wr[t * 32 + lane];
        float4 u = ur[t * 32 + lane];
        acc += w.x * u.x + w.y * u.y + w.z * u.z + w.w * u.w;
    }
#pragma unroll
    for (int o = 16; o > 0; o >>= 1) acc += __shfl_xor_sync(~0u, acc, o);
    if (lane == 0) g_o1[b * HDIM + j] = acc + bv[j] * g_A[b * HN + h];
}

// ---------------------------------------------------------------------------
// K5: res[b,i] = Wf[i,:] . o1[b,:] + bf[i]   warp per (i,b)
// ---------------------------------------------------------------------------
__global__ void k5_final(const float* __restrict__ Wf,
                         const float* __restrict__ bf,
                         float* __restrict__ res) {
    int gw   = (blockIdx.x * blockDim.x + threadIdx.x) >> 5;
    int lane = threadIdx.x & 31;
    if (gw >= HDIM * BATCH) return;
    int b = gw & 15, i = gw >> 4;
    const float4* wr = (const float4*)(Wf + (size_t)i * HDIM);
    const float4* orow = (const float4*)(g_o1 + b * HDIM);
    float acc = 0.f;
#pragma unroll
    for (int t = 0; t < 8; t++) {
        float4 w = wr[t * 32 + lane];
        float4 o = orow[t * 32 + lane];
        acc += w.x * o.x + w.y * o.y + w.z * o.z + w.w * o.w;
    }
#pragma unroll
    for (int o = 16; o > 0; o >>= 1) acc += __shfl_xor_sync(~0u, acc, o);
    if (lane == 0) res[b * HDIM + i] = acc + bf[i];
}

// ---------------------------------------------------------------------------
// launch
// ---------------------------------------------------------------------------
extern "C" void kernel_launch(void* const* d_in, const int* in_sizes, int n_in,
                              void* d_out, int out_size) {
    const float* query = (const float*)d_in[0];
    const float* key_  = (const float*)d_in[1];
    const float* value = (const float*)d_in[2];
    const float* Wq    = (const float*)d_in[3];
    const float* bq    = (const float*)d_in[4];
    const float* Wk    = (const float*)d_in[5];
    const float* bk    = (const float*)d_in[6];
    const float* Wv    = (const float*)d_in[7];
    const float* bv    = (const float*)d_in[8];
    const float* Wf    = (const float*)d_in[9];
    const float* bf    = (const float*)d_in[10];
    float* out = (float*)d_out;

    // kbuf 16384 + part 2048 + c 16 floats
    const int k3a_smem = (2 * 8 * HDIM + 2048 + 16) * 4;   // 73792 B
    static bool attr_set = false;
    if (!attr_set) {
        cudaFuncSetAttribute(k3a_scores, cudaFuncAttributeMaxDynamicSharedMemorySize, k3a_smem);
        attr_set = true;
    }

    k1_q<<<(BATCH * HDIM * 32 + 255) / 256, 256>>>(query, Wq, bq);
    k2_w<<<HN * BATCH, 256>>>(Wk, bk);
    {
        dim3 grid_a(SEQ / 128, BATCH);
        k3a_scores<<<grid_a, 256, k3a_smem>>>(key_);
        dim3 grid_b(SEQ / 256, BATCH);
        k3b_accum<<<grid_b, 256>>>(value);
    }
    k4_out<<<(HDIM * BATCH * 32 + 255) / 256, 256>>>(Wv, bv);
    k5_final<<<(HDIM * BATCH * 32 + 255) / 256, 256>>>(Wf, bf, out);
}